// round 11
// baseline (speedup 1.0000x reference)
#include <cuda_runtime.h>
#include <cuda_fp16.h>
#include <cstdint>

#define TT   2048
#define HQn  16
#define HKVn 4
#define DH   128
#define BM   128
#define BN   64
#define NTH  256
#define CHUNK_TILES 8           // max key-tiles per split-K chunk
#define MAXCH 4                 // max chunks per (head, q-tile)

// ---------------- smem layout (bytes) ----------------
#define OFF_Q    0
#define OFF_K(s) (32768 + (s) * 32768)
#define OFF_V(s) (OFF_K(s) + 16384)
#define OFF_LB   98304            // reducer l staging (512B)
#define OFF_FLAG 98816            // int flag for reducer election
#define SMEM_TOTAL 99328

// ---------------- global scratch ----------------
__device__ __align__(16) __half g_qh[(size_t)TT * HQn * DH];
__device__ __align__(16) __half g_kh[(size_t)TT * HKVn * DH];
__device__ __align__(16) __half g_vh[(size_t)TT * HKVn * DH];
// split-K partials: slot = ((head*16 + qt)*MAXCH + chunk)
__device__ __align__(16) float g_po[(size_t)HQn * 16 * MAXCH * BM * DH];
__device__ float g_pl[(size_t)HQn * 16 * MAXCH * BM];
__device__ int   g_cnt[HQn * 16];   // zero-init; reducer resets after use

// ---------------- helpers ----------------
__device__ __forceinline__ uint32_t smem_u32(const void* p) {
    uint32_t a;
    asm("{ .reg .u64 t; cvta.to.shared.u64 t, %1; cvt.u32.u64 %0, t; }" : "=r"(a) : "l"(p));
    return a;
}
__device__ __forceinline__ int swz(int c, int row) {      // 16B-chunk swizzle
    return (c & 8) | ((c ^ row) & 7);
}
__device__ __forceinline__ void cpa(uint32_t dst, const void* src) {
    asm volatile("cp.async.cg.shared.global [%0], [%1], 16;" :: "r"(dst), "l"(src));
}
#define CP_COMMIT() asm volatile("cp.async.commit_group;" ::: "memory")
#define CP_WAIT0()  asm volatile("cp.async.wait_group 0;" ::: "memory")

__device__ __forceinline__ void ldsm4(uint32_t* r, uint32_t a) {
    asm volatile("ldmatrix.sync.aligned.m8n8.x4.shared.b16 {%0,%1,%2,%3}, [%4];"
                 : "=r"(r[0]), "=r"(r[1]), "=r"(r[2]), "=r"(r[3]) : "r"(a));
}
__device__ __forceinline__ void ldsm4t(uint32_t* r, uint32_t a) {
    asm volatile("ldmatrix.sync.aligned.m8n8.x4.trans.shared.b16 {%0,%1,%2,%3}, [%4];"
                 : "=r"(r[0]), "=r"(r[1]), "=r"(r[2]), "=r"(r[3]) : "r"(a));
}
__device__ __forceinline__ void hmma(float* d, const uint32_t* a, const uint32_t* b) {
    asm volatile("mma.sync.aligned.m16n8k16.row.col.f32.f16.f16.f32 "
                 "{%0,%1,%2,%3}, {%4,%5,%6,%7}, {%8,%9}, {%0,%1,%2,%3};"
                 : "+f"(d[0]), "+f"(d[1]), "+f"(d[2]), "+f"(d[3])
                 : "r"(a[0]), "r"(a[1]), "r"(a[2]), "r"(a[3]), "r"(b[0]), "r"(b[1]));
}
__device__ __forceinline__ float ex2(float x) {
    float r;
    asm("ex2.approx.ftz.f32 %0, %1;" : "=f"(r) : "f"(x));
    return r;
}
__device__ __forceinline__ uint32_t h2pack(float a, float b) {
    __half2 h = __floats2half2_rn(a, b);
    return *(uint32_t*)&h;
}

// ---------------- fused prepass: rope(Q), rope(K), conv(V) ----------------
#define QBLK ((TT * HQn * 64) / 256)     // 8192
#define KBLK ((TT * HKVn * 64) / 256)    // 2048
#define VBLK ((TT * HKVn * DH) / 1024)   // 1024
__global__ void prep_kernel(const float* __restrict__ q, const float* __restrict__ k,
                            const float* __restrict__ v, const float* __restrict__ cs,
                            const float* __restrict__ sn) {
    int b = blockIdx.x;
    if (b < QBLK) {
        int lin = b * 256 + threadIdx.x;
        int row = lin >> 6, j = lin & 63;
        int tq = row >> 4;
        size_t base = (size_t)row * DH;
        float2 xv = *(const float2*)(q + base + 2 * j);
        float2 xo = *(const float2*)(q + base + ((2 * j) ^ 64));
        int ci = (2 * j) & 63;
        float c0 = cs[tq * 64 + ci],     s0 = sn[tq * 64 + ci];
        float c1 = cs[tq * 64 + ci + 1], s1 = sn[tq * 64 + ci + 1];
        float sg = (j < 32) ? -1.f : 1.f;
        *(__half2*)(g_qh + base + 2 * j) =
            __floats2half2_rn(xv.x * c0 + sg * xo.x * s0, xv.y * c1 + sg * xo.y * s1);
    } else if (b < QBLK + KBLK) {
        int lin = (b - QBLK) * 256 + threadIdx.x;
        int row = lin >> 6, j = lin & 63;
        int tk = row >> 2;
        size_t base = (size_t)row * DH;
        float2 xv = *(const float2*)(k + base + 2 * j);
        float2 xo = *(const float2*)(k + base + ((2 * j) ^ 64));
        int ci = (2 * j) & 63;
        float c0 = cs[tk * 64 + ci],     s0 = sn[tk * 64 + ci];
        float c1 = cs[tk * 64 + ci + 1], s1 = sn[tk * 64 + ci + 1];
        float sg = (j < 32) ? -1.f : 1.f;
        *(__half2*)(g_kh + base + 2 * j) =
            __floats2half2_rn(xv.x * c0 + sg * xo.x * s0, xv.y * c1 + sg * xo.y * s1);
    } else {
        size_t i = ((size_t)(b - QBLK - KBLK) * 256 + threadIdx.x) * 4;
        float4 f = *(const float4*)(v + i);
        ((__half2*)(g_vh + i))[0] = __floats2half2_rn(f.x, f.y);
        ((__half2*)(g_vh + i))[1] = __floats2half2_rn(f.z, f.w);
    }
}

// ---------------- K/V tile loader (cp.async) ----------------
__device__ __forceinline__ void load_tile(uint32_t sb, int t0, int stage, int hk, int tid) {
    const uint32_t Kb = sb + OFF_K(stage), Vb = sb + OFF_V(stage);
#pragma unroll
    for (int j = 0; j < 4; ++j) {
        int idx = tid + j * 256;
        int row = idx >> 4, c = idx & 15;
        size_t g = ((size_t)(t0 + row) * HKVn + hk) * DH + c * 8;
        uint32_t so = row * 256 + swz(c, row) * 16;
        cpa(Kb + so, g_kh + g);
        cpa(Vb + so, g_vh + g);
    }
}

// ---------------- main attention kernel (split-K, fused reduce) ----------------
__global__ __launch_bounds__(NTH, 2)
void attn_kernel(const int* __restrict__ qranges,
                 const int* __restrict__ kranges,
                 int nR, float* __restrict__ out) {
    extern __shared__ char smem[];
    const uint32_t sb = smem_u32(smem);
    const int tid  = threadIdx.x;
    const int wid  = tid >> 5;
    const int lane = tid & 31;
    const int g    = lane >> 2;
    const int tq4  = lane & 3;

    const int head  = blockIdx.x & 15;
    const int chunk = (blockIdx.x >> 4) & 3;
    const int qt    = 15 - (blockIdx.x >> 6);   // heavy-first
    const int q0    = qt * BM;
    const int hk    = head >> 2;

    int kEnd = 0;
    for (int r = 0; r < nR; ++r) {
        int qs = qranges[2 * r], qe = qranges[2 * r + 1];
        if (q0 >= qs && q0 < qe) { int ke = kranges[2 * r + 1]; if (ke > kEnd) kEnd = ke; }
    }
    const int nt  = kEnd / BN;
    const int nch = (nt + CHUNK_TILES - 1) / CHUNK_TILES;
    if (chunk >= nch) return;
    const int csz = (nt + nch - 1) / nch;       // balanced chunk size
    const int tS = chunk * csz;
    const int tE = min(nt, tS + csz);

    const int mwBase = wid * 16;               // 16 q rows per warp, all 64 keys

    // ---- prologue: Q + first tile, one cp.async group ----
#pragma unroll
    for (int j = 0; j < 8; ++j) {
        int idx = tid + j * 256;
        int row = idx >> 4, c = idx & 15;
        size_t gof = ((size_t)(q0 + row) * HQn + head) * DH + c * 8;
        cpa(sb + OFF_Q + row * 256 + swz(c, row) * 16, g_qh + gof);
    }
    load_tile(sb, tS * BN, 0, hk, tid);
    CP_COMMIT();

    float O[16][4];          // 16 rows x 128 d
    float Lacc[4];           // row-sum accumulator via ones-HMMA (col 0)
    const uint32_t ones2[2] = { 0x3C003C00u, 0x3C003C00u };
#pragma unroll
    for (int nf = 0; nf < 16; ++nf)
#pragma unroll
        for (int e = 0; e < 4; ++e) O[nf][e] = 0.f;
#pragma unroll
    for (int e = 0; e < 4; ++e) Lacc[e] = 0.f;

    const float kC = 0.127532019f;   // log2(e)/sqrt(128)

#pragma unroll 2
    for (int t = tS; t < tE; ++t) {
        const int s = (t - tS) & 1;

        CP_WAIT0();
        __syncthreads();                       // tile t ready; stage s free everywhere
        if (t + 1 < tE) { load_tile(sb, (t + 1) * BN, s ^ 1, hk, tid); CP_COMMIT(); }

        // ---------- QK: S(m16 x n64) = Q . K^T ----------
        float S[8][4];
#pragma unroll
        for (int nf = 0; nf < 8; ++nf)
#pragma unroll
            for (int e = 0; e < 4; ++e) S[nf][e] = 0.f;

        const uint32_t Kb = sb + OFF_K(s);
        const uint32_t Qb = sb + OFF_Q;
#pragma unroll
        for (int ks = 0; ks < 8; ++ks) {
            // burst: 1 Q ldsm + 4 K ldsm (all 64 keys), then 8 HMMA
            uint32_t a[4];
            uint32_t kb[16];
            {
                int rowA = mwBase + (lane & 15);
                int ch = 2 * ks + (lane >> 4);
                ldsm4(a, Qb + rowA * 256 + swz(ch, rowA) * 16);
            }
#pragma unroll
            for (int kk = 0; kk < 4; ++kk) {
                int rowK = kk * 16 + ((lane >> 4) << 3) + (lane & 7);
                int ch = 2 * ks + ((lane >> 3) & 1);
                ldsm4(kb + 4 * kk, Kb + rowK * 256 + swz(ch, rowK) * 16);
            }
#pragma unroll
            for (int nf = 0; nf < 8; ++nf)
                hmma(S[nf], a, kb + 2 * nf);
        }

        // ---------- softmax: S C-frags -> P A-frags in registers (FA-2 trick) ----------
        uint32_t Pa[4][4];
#pragma unroll
        for (int j = 0; j < 4; ++j) {
            float e00 = ex2(S[2 * j][0] * kC),     e01 = ex2(S[2 * j][1] * kC);
            float e02 = ex2(S[2 * j][2] * kC),     e03 = ex2(S[2 * j][3] * kC);
            float e10 = ex2(S[2 * j + 1][0] * kC), e11 = ex2(S[2 * j + 1][1] * kC);
            float e12 = ex2(S[2 * j + 1][2] * kC), e13 = ex2(S[2 * j + 1][3] * kC);
            Pa[j][0] = h2pack(e00, e01);
            Pa[j][1] = h2pack(e02, e03);
            Pa[j][2] = h2pack(e10, e11);
            Pa[j][3] = h2pack(e12, e13);
        }

        // ---------- PV: O(m16 x d128) += P . V ; l via ones column ----------
        const uint32_t Vb = sb + OFF_V(s);
#pragma unroll
        for (int ks = 0; ks < 4; ++ks) {
            // burst: 8 V ldsm4t (all 128 d), Lacc HMMA overlaps loads, then 16 HMMA
            uint32_t vb[32];
            hmma(Lacc, Pa[ks], ones2);
#pragma unroll
            for (int j = 0; j < 8; ++j) {
                int rowV = ks * 16 + (lane & 15);
                int cd = j * 2 + (lane >> 4);
                ldsm4t(vb + 4 * j, Vb + rowV * 256 + swz(cd, rowV) * 16);
            }
#pragma unroll
            for (int nf = 0; nf < 16; ++nf)
                hmma(O[nf], Pa[ks], vb + 2 * nf);
        }
    }

    // l per row: col 0 of Lacc lives in tq4==0 lanes (c0 -> row rg, c2 -> row rg+8)
    const int rg = mwBase + g;
    const int rh = rg + 8;
    const float lg = __shfl_sync(0xffffffffu, Lacc[0], lane & ~3);
    const float lh = __shfl_sync(0xffffffffu, Lacc[2], lane & ~3);

    if (nch == 1) {
        // ---- direct epilogue: normalize + store ----
        float ig = 1.0f / lg;
        float ih = 1.0f / lh;
        float* og = out + ((size_t)(q0 + rg) * HQn + head) * DH;
        float* oh = out + ((size_t)(q0 + rh) * HQn + head) * DH;
#pragma unroll
        for (int nf = 0; nf < 16; ++nf) {
            int d = nf * 8 + 2 * tq4;
            *(float2*)(og + d) = make_float2(O[nf][0] * ig, O[nf][1] * ig);
            *(float2*)(oh + d) = make_float2(O[nf][2] * ih, O[nf][3] * ih);
        }
        return;
    }

    // ---- split epilogue: unnormalized partial O + l to scratch ----
    const int hq16 = head * 16 + qt;
    const size_t base = (size_t)hq16 * MAXCH;
    {
        float* po = g_po + (base + chunk) * (BM * DH);
        float* pl = g_pl + (base + chunk) * BM;
        if (tq4 == 0) { pl[rg] = lg; pl[rh] = lh; }
        float* og = po + rg * DH;
        float* oh = po + rh * DH;
#pragma unroll
        for (int nf = 0; nf < 16; ++nf) {
            int d = nf * 8 + 2 * tq4;
            *(float2*)(og + d) = make_float2(O[nf][0], O[nf][1]);
            *(float2*)(oh + d) = make_float2(O[nf][2], O[nf][3]);
        }
    }

    // ---- election: last-arriving chunk reduces ----
    __threadfence();
    __syncthreads();
    int* flag = (int*)(smem + OFF_FLAG);
    if (tid == 0) *flag = atomicAdd(&g_cnt[hq16], 1);
    __syncthreads();
    if (*flag != nch - 1) return;

    // this CTA is the reducer
    if (tid == 0) g_cnt[hq16] = 0;             // reset for next graph replay
    __threadfence();
    float* linv = (float*)(smem + OFF_LB);
    if (tid < BM) {
        float l = 0.f;
        for (int c = 0; c < nch; ++c) l += g_pl[(base + c) * BM + tid];
        linv[tid] = 1.0f / l;
    }
    __syncthreads();

    const float4* po4 = (const float4*)(g_po + base * (BM * DH));
#pragma unroll
    for (int i = 0; i < 16; ++i) {
        int idx = tid + i * 256;               // 4096 float4 = 128x128
        int row = idx >> 5;
        float4 acc = po4[idx];
        for (int c = 1; c < nch; ++c) {
            float4 w = po4[(size_t)c * (BM * DH / 4) + idx];
            acc.x += w.x; acc.y += w.y; acc.z += w.z; acc.w += w.w;
        }
        float sc = linv[row];
        acc.x *= sc; acc.y *= sc; acc.z *= sc; acc.w *= sc;
        int d = (idx & 31) * 4;
        *(float4*)(out + ((size_t)(q0 + row) * HQn + head) * DH + d) = acc;
    }
}

extern "C" void kernel_launch(void* const* d_in, const int* in_sizes, int n_in,
                              void* d_out, int out_size) {
    const float* q  = (const float*)d_in[0];
    const float* k  = (const float*)d_in[1];
    const float* v  = (const float*)d_in[2];
    const float* cs = (const float*)d_in[3];
    const float* sn = (const float*)d_in[4];
    const int*   qr = (const int*)d_in[5];
    const int*   kr = (const int*)d_in[6];
    const int nR = in_sizes[5] / 2;
    float* out = (float*)d_out;

    cudaFuncSetAttribute(attn_kernel,
                         cudaFuncAttributeMaxDynamicSharedMemorySize, SMEM_TOTAL);

    prep_kernel<<<QBLK + KBLK + VBLK, 256>>>(q, k, v, cs, sn);
    attn_kernel<<<(TT / BM) * HQn * MAXCH, NTH, SMEM_TOTAL>>>(qr, kr, nR, out);
}

// round 12
// speedup vs baseline: 1.0506x; 1.0506x over previous
#include <cuda_runtime.h>
#include <cuda_fp16.h>
#include <cstdint>

#define TT   2048
#define HQn  16
#define HKVn 4
#define DH   128
#define BM   128
#define BN   64
#define NTH  256
#define CHUNK_TILES 16          // max key-tiles per split-K chunk
#define MAXCH 2                 // max chunks per (head, q-tile)

// ---------------- smem layout (bytes) ----------------
#define OFF_Q    0
#define OFF_K(s) (32768 + (s) * 32768)
#define OFF_V(s) (OFF_K(s) + 16384)
#define OFF_LB   98304            // reducer l staging (512B)
#define OFF_FLAG 98816            // int flag for reducer election
#define SMEM_TOTAL 99328

// ---------------- global scratch ----------------
__device__ __align__(16) __half g_qh[(size_t)TT * HQn * DH];
__device__ __align__(16) __half g_kh[(size_t)TT * HKVn * DH];
__device__ __align__(16) __half g_vh[(size_t)TT * HKVn * DH];
// split-K partials: slot = ((head*16 + qt)*MAXCH + chunk)
__device__ __align__(16) float g_po[(size_t)HQn * 16 * MAXCH * BM * DH];
__device__ float g_pl[(size_t)HQn * 16 * MAXCH * BM];
__device__ int   g_cnt[HQn * 16];   // zero-init; reducer resets after use

// ---------------- helpers ----------------
__device__ __forceinline__ uint32_t smem_u32(const void* p) {
    uint32_t a;
    asm("{ .reg .u64 t; cvta.to.shared.u64 t, %1; cvt.u32.u64 %0, t; }" : "=r"(a) : "l"(p));
    return a;
}
__device__ __forceinline__ int swz(int c, int row) {      // 16B-chunk swizzle
    return (c & 8) | ((c ^ row) & 7);
}
__device__ __forceinline__ void cpa(uint32_t dst, const void* src) {
    asm volatile("cp.async.cg.shared.global [%0], [%1], 16;" :: "r"(dst), "l"(src));
}
#define CP_COMMIT() asm volatile("cp.async.commit_group;" ::: "memory")
#define CP_WAIT0()  asm volatile("cp.async.wait_group 0;" ::: "memory")

__device__ __forceinline__ void ldsm4(uint32_t* r, uint32_t a) {
    asm volatile("ldmatrix.sync.aligned.m8n8.x4.shared.b16 {%0,%1,%2,%3}, [%4];"
                 : "=r"(r[0]), "=r"(r[1]), "=r"(r[2]), "=r"(r[3]) : "r"(a));
}
__device__ __forceinline__ void ldsm4t(uint32_t* r, uint32_t a) {
    asm volatile("ldmatrix.sync.aligned.m8n8.x4.trans.shared.b16 {%0,%1,%2,%3}, [%4];"
                 : "=r"(r[0]), "=r"(r[1]), "=r"(r[2]), "=r"(r[3]) : "r"(a));
}
__device__ __forceinline__ void hmma(float* d, const uint32_t* a, const uint32_t* b) {
    asm volatile("mma.sync.aligned.m16n8k16.row.col.f32.f16.f16.f32 "
                 "{%0,%1,%2,%3}, {%4,%5,%6,%7}, {%8,%9}, {%0,%1,%2,%3};"
                 : "+f"(d[0]), "+f"(d[1]), "+f"(d[2]), "+f"(d[3])
                 : "r"(a[0]), "r"(a[1]), "r"(a[2]), "r"(a[3]), "r"(b[0]), "r"(b[1]));
}
__device__ __forceinline__ float ex2(float x) {
    float r;
    asm("ex2.approx.ftz.f32 %0, %1;" : "=f"(r) : "f"(x));
    return r;
}
__device__ __forceinline__ uint32_t h2pack(float a, float b) {
    __half2 h = __floats2half2_rn(a, b);
    return *(uint32_t*)&h;
}

// ---------------- fused prepass: rope(Q), rope(K), conv(V) ----------------
#define QBLK ((TT * HQn * 64) / 256)     // 8192
#define KBLK ((TT * HKVn * 64) / 256)    // 2048
#define VBLK ((TT * HKVn * DH) / 1024)   // 1024
__global__ void prep_kernel(const float* __restrict__ q, const float* __restrict__ k,
                            const float* __restrict__ v, const float* __restrict__ cs,
                            const float* __restrict__ sn) {
    int b = blockIdx.x;
    if (b < QBLK) {
        int lin = b * 256 + threadIdx.x;
        int row = lin >> 6, j = lin & 63;
        int tq = row >> 4;
        size_t base = (size_t)row * DH;
        float2 xv = *(const float2*)(q + base + 2 * j);
        float2 xo = *(const float2*)(q + base + ((2 * j) ^ 64));
        int ci = (2 * j) & 63;
        float c0 = cs[tq * 64 + ci],     s0 = sn[tq * 64 + ci];
        float c1 = cs[tq * 64 + ci + 1], s1 = sn[tq * 64 + ci + 1];
        float sg = (j < 32) ? -1.f : 1.f;
        *(__half2*)(g_qh + base + 2 * j) =
            __floats2half2_rn(xv.x * c0 + sg * xo.x * s0, xv.y * c1 + sg * xo.y * s1);
    } else if (b < QBLK + KBLK) {
        int lin = (b - QBLK) * 256 + threadIdx.x;
        int row = lin >> 6, j = lin & 63;
        int tk = row >> 2;
        size_t base = (size_t)row * DH;
        float2 xv = *(const float2*)(k + base + 2 * j);
        float2 xo = *(const float2*)(k + base + ((2 * j) ^ 64));
        int ci = (2 * j) & 63;
        float c0 = cs[tk * 64 + ci],     s0 = sn[tk * 64 + ci];
        float c1 = cs[tk * 64 + ci + 1], s1 = sn[tk * 64 + ci + 1];
        float sg = (j < 32) ? -1.f : 1.f;
        *(__half2*)(g_kh + base + 2 * j) =
            __floats2half2_rn(xv.x * c0 + sg * xo.x * s0, xv.y * c1 + sg * xo.y * s1);
    } else {
        size_t i = ((size_t)(b - QBLK - KBLK) * 256 + threadIdx.x) * 4;
        float4 f = *(const float4*)(v + i);
        ((__half2*)(g_vh + i))[0] = __floats2half2_rn(f.x, f.y);
        ((__half2*)(g_vh + i))[1] = __floats2half2_rn(f.z, f.w);
    }
}

// ---------------- K/V tile loader (cp.async) ----------------
__device__ __forceinline__ void load_tile(uint32_t sb, int t0, int stage, int hk, int tid) {
    const uint32_t Kb = sb + OFF_K(stage), Vb = sb + OFF_V(stage);
#pragma unroll
    for (int j = 0; j < 4; ++j) {
        int idx = tid + j * 256;
        int row = idx >> 4, c = idx & 15;
        size_t g = ((size_t)(t0 + row) * HKVn + hk) * DH + c * 8;
        uint32_t so = row * 256 + swz(c, row) * 16;
        cpa(Kb + so, g_kh + g);
        cpa(Vb + so, g_vh + g);
    }
}

// ---------------- main attention kernel (split-K, fused reduce) ----------------
__global__ __launch_bounds__(NTH, 2)
void attn_kernel(const int* __restrict__ qranges,
                 const int* __restrict__ kranges,
                 int nR, float* __restrict__ out) {
    extern __shared__ char smem[];
    const uint32_t sb = smem_u32(smem);
    const int tid  = threadIdx.x;
    const int wid  = tid >> 5;
    const int lane = tid & 31;
    const int g    = lane >> 2;
    const int tq4  = lane & 3;

    const int head  = blockIdx.x & 15;
    const int chunk = (blockIdx.x >> 4) & (MAXCH - 1);
    const int qt    = 15 - (blockIdx.x >> 5);   // heavy-first
    const int q0    = qt * BM;
    const int hk    = head >> 2;

    int kEnd = 0;
    for (int r = 0; r < nR; ++r) {
        int qs = qranges[2 * r], qe = qranges[2 * r + 1];
        if (q0 >= qs && q0 < qe) { int ke = kranges[2 * r + 1]; if (ke > kEnd) kEnd = ke; }
    }
    const int nt  = kEnd / BN;
    const int nch = (nt + CHUNK_TILES - 1) / CHUNK_TILES;
    if (chunk >= nch) return;
    const int csz = (nt + nch - 1) / nch;       // balanced chunk size
    const int tS = chunk * csz;
    const int tE = min(nt, tS + csz);

    const int mwBase = wid * 16;               // 16 q rows per warp, all 64 keys

    // ---- prologue: Q + first tile, one cp.async group ----
#pragma unroll
    for (int j = 0; j < 8; ++j) {
        int idx = tid + j * 256;
        int row = idx >> 4, c = idx & 15;
        size_t gof = ((size_t)(q0 + row) * HQn + head) * DH + c * 8;
        cpa(sb + OFF_Q + row * 256 + swz(c, row) * 16, g_qh + gof);
    }
    load_tile(sb, tS * BN, 0, hk, tid);
    CP_COMMIT();

    float O[16][4];          // 16 rows x 128 d
    float Lacc[4];           // row-sum accumulator via ones-HMMA (col 0)
    const uint32_t ones2[2] = { 0x3C003C00u, 0x3C003C00u };
#pragma unroll
    for (int nf = 0; nf < 16; ++nf)
#pragma unroll
        for (int e = 0; e < 4; ++e) O[nf][e] = 0.f;
#pragma unroll
    for (int e = 0; e < 4; ++e) Lacc[e] = 0.f;

    const float kC = 0.127532019f;   // log2(e)/sqrt(128)

    for (int t = tS; t < tE; ++t) {
        const int s = (t - tS) & 1;

        CP_WAIT0();
        __syncthreads();                       // tile t ready; stage s free everywhere
        if (t + 1 < tE) { load_tile(sb, (t + 1) * BN, s ^ 1, hk, tid); CP_COMMIT(); }

        // ---------- QK: S(m16 x n64) = Q . K^T ----------
        float S[8][4];
#pragma unroll
        for (int nf = 0; nf < 8; ++nf)
#pragma unroll
            for (int e = 0; e < 4; ++e) S[nf][e] = 0.f;

        const uint32_t Kb = sb + OFF_K(s);
        const uint32_t Qb = sb + OFF_Q;
#pragma unroll
        for (int ks = 0; ks < 8; ++ks) {
            uint32_t a[4];
            {
                int rowA = mwBase + (lane & 15);
                int ch = 2 * ks + (lane >> 4);
                ldsm4(a, Qb + rowA * 256 + swz(ch, rowA) * 16);
            }
#pragma unroll
            for (int half = 0; half < 2; ++half) {
                uint32_t kb[8];
#pragma unroll
                for (int kk = 0; kk < 2; ++kk) {
                    int rowK = (half * 2 + kk) * 16 + ((lane >> 4) << 3) + (lane & 7);
                    int ch = 2 * ks + ((lane >> 3) & 1);
                    ldsm4(kb + 4 * kk, Kb + rowK * 256 + swz(ch, rowK) * 16);
                }
                hmma(S[half * 4 + 0], a, kb + 0);
                hmma(S[half * 4 + 1], a, kb + 2);
                hmma(S[half * 4 + 2], a, kb + 4);
                hmma(S[half * 4 + 3], a, kb + 6);
            }
        }

        // ---------- softmax: S C-frags -> P A-frags in registers (FA-2 trick) ----------
        uint32_t Pa[4][4];
#pragma unroll
        for (int j = 0; j < 4; ++j) {
            float e00 = ex2(S[2 * j][0] * kC),     e01 = ex2(S[2 * j][1] * kC);
            float e02 = ex2(S[2 * j][2] * kC),     e03 = ex2(S[2 * j][3] * kC);
            float e10 = ex2(S[2 * j + 1][0] * kC), e11 = ex2(S[2 * j + 1][1] * kC);
            float e12 = ex2(S[2 * j + 1][2] * kC), e13 = ex2(S[2 * j + 1][3] * kC);
            Pa[j][0] = h2pack(e00, e01);
            Pa[j][1] = h2pack(e02, e03);
            Pa[j][2] = h2pack(e10, e11);
            Pa[j][3] = h2pack(e12, e13);
        }

        // ---------- PV: O(m16 x d128) += P . V ; l via ones column ----------
        const uint32_t Vb = sb + OFF_V(s);
#pragma unroll
        for (int ks = 0; ks < 4; ++ks) {
            hmma(Lacc, Pa[ks], ones2);
#pragma unroll
            for (int half = 0; half < 2; ++half) {
                uint32_t vb[16];
#pragma unroll
                for (int nfp = 0; nfp < 4; ++nfp) {
                    int rowV = ks * 16 + (lane & 15);
                    int cd = half * 8 + nfp * 2 + (lane >> 4);
                    ldsm4t(vb + nfp * 4, Vb + rowV * 256 + swz(cd, rowV) * 16);
                }
#pragma unroll
                for (int nf = 0; nf < 8; ++nf)
                    hmma(O[half * 8 + nf], Pa[ks], vb + nf * 2);
            }
        }
    }

    // l per row: col 0 of Lacc lives in tq4==0 lanes (c0 -> row rg, c2 -> row rg+8)
    const int rg = mwBase + g;
    const int rh = rg + 8;
    const float lg = __shfl_sync(0xffffffffu, Lacc[0], lane & ~3);
    const float lh = __shfl_sync(0xffffffffu, Lacc[2], lane & ~3);

    if (nch == 1) {
        // ---- direct epilogue: normalize + store ----
        float ig = 1.0f / lg;
        float ih = 1.0f / lh;
        float* og = out + ((size_t)(q0 + rg) * HQn + head) * DH;
        float* oh = out + ((size_t)(q0 + rh) * HQn + head) * DH;
#pragma unroll
        for (int nf = 0; nf < 16; ++nf) {
            int d = nf * 8 + 2 * tq4;
            *(float2*)(og + d) = make_float2(O[nf][0] * ig, O[nf][1] * ig);
            *(float2*)(oh + d) = make_float2(O[nf][2] * ih, O[nf][3] * ih);
        }
        return;
    }

    // ---- split epilogue: unnormalized partial O + l to scratch ----
    const int hq16 = head * 16 + qt;
    const size_t base = (size_t)hq16 * MAXCH;
    {
        float* po = g_po + (base + chunk) * (BM * DH);
        float* pl = g_pl + (base + chunk) * BM;
        if (tq4 == 0) { pl[rg] = lg; pl[rh] = lh; }
        float* og = po + rg * DH;
        float* oh = po + rh * DH;
#pragma unroll
        for (int nf = 0; nf < 16; ++nf) {
            int d = nf * 8 + 2 * tq4;
            *(float2*)(og + d) = make_float2(O[nf][0], O[nf][1]);
            *(float2*)(oh + d) = make_float2(O[nf][2], O[nf][3]);
        }
    }

    // ---- election: last-arriving chunk reduces ----
    __threadfence();
    __syncthreads();
    int* flag = (int*)(smem + OFF_FLAG);
    if (tid == 0) *flag = atomicAdd(&g_cnt[hq16], 1);
    __syncthreads();
    if (*flag != nch - 1) return;

    // this CTA is the reducer
    if (tid == 0) g_cnt[hq16] = 0;             // reset for next graph replay
    __threadfence();
    float* linv = (float*)(smem + OFF_LB);
    if (tid < BM) {
        float l = 0.f;
        for (int c = 0; c < nch; ++c) l += g_pl[(base + c) * BM + tid];
        linv[tid] = 1.0f / l;
    }
    __syncthreads();

    const float4* po4 = (const float4*)(g_po + base * (BM * DH));
#pragma unroll
    for (int i = 0; i < 16; ++i) {
        int idx = tid + i * 256;               // 4096 float4 = 128x128
        int row = idx >> 5;
        float4 acc = po4[idx];
        for (int c = 1; c < nch; ++c) {
            float4 w = po4[(size_t)c * (BM * DH / 4) + idx];
            acc.x += w.x; acc.y += w.y; acc.z += w.z; acc.w += w.w;
        }
        float sc = linv[row];
        acc.x *= sc; acc.y *= sc; acc.z *= sc; acc.w *= sc;
        int d = (idx & 31) * 4;
        *(float4*)(out + ((size_t)(q0 + row) * HQn + head) * DH + d) = acc;
    }
}

extern "C" void kernel_launch(void* const* d_in, const int* in_sizes, int n_in,
                              void* d_out, int out_size) {
    const float* q  = (const float*)d_in[0];
    const float* k  = (const float*)d_in[1];
    const float* v  = (const float*)d_in[2];
    const float* cs = (const float*)d_in[3];
    const float* sn = (const float*)d_in[4];
    const int*   qr = (const int*)d_in[5];
    const int*   kr = (const int*)d_in[6];
    const int nR = in_sizes[5] / 2;
    float* out = (float*)d_out;

    cudaFuncSetAttribute(attn_kernel,
                         cudaFuncAttributeMaxDynamicSharedMemorySize, SMEM_TOTAL);

    prep_kernel<<<QBLK + KBLK + VBLK, 256>>>(q, k, v, cs, sn);
    attn_kernel<<<(TT / BM) * HQn * MAXCH, NTH, SMEM_TOTAL>>>(qr, kr, nR, out);
}

// round 13
// speedup vs baseline: 1.0709x; 1.0193x over previous
#include <cuda_runtime.h>
#include <cuda_fp16.h>
#include <cstdint>

#define TT   2048
#define HQn  16
#define HKVn 4
#define DH   128
#define BM   128
#define BN   64
#define NTH  256
#define CHUNK_TILES 16          // max key-tiles per split-K chunk
#define MAXCH 2                 // max chunks per (head, q-tile)

// ---------------- smem layout (bytes) ----------------
#define OFF_Q    0                          // 32KB (only used in prologue)
#define OFF_K(s) (32768 + (s) * 32768)      // 3 stages x (16K K + 16K V)
#define OFF_V(s) (OFF_K(s) + 16384)
#define OFF_LB   131072                     // reducer l staging (512B)
#define OFF_FLAG 131584                     // int flag for reducer election
#define SMEM_TOTAL 132096

// ---------------- global scratch ----------------
__device__ __align__(16) __half g_qh[(size_t)TT * HQn * DH];
__device__ __align__(16) __half g_kh[(size_t)TT * HKVn * DH];
__device__ __align__(16) __half g_vh[(size_t)TT * HKVn * DH];
// split-K partials: slot = ((head*16 + qt)*MAXCH + chunk)
__device__ __align__(16) float g_po[(size_t)HQn * 16 * MAXCH * BM * DH];
__device__ float g_pl[(size_t)HQn * 16 * MAXCH * BM];
__device__ int   g_cnt[HQn * 16];   // zero-init; reducer resets after use

// ---------------- helpers ----------------
__device__ __forceinline__ uint32_t smem_u32(const void* p) {
    uint32_t a;
    asm("{ .reg .u64 t; cvta.to.shared.u64 t, %1; cvt.u32.u64 %0, t; }" : "=r"(a) : "l"(p));
    return a;
}
__device__ __forceinline__ int swz(int c, int row) {      // 16B-chunk swizzle
    return (c & 8) | ((c ^ row) & 7);
}
__device__ __forceinline__ void cpa(uint32_t dst, const void* src) {
    asm volatile("cp.async.cg.shared.global [%0], [%1], 16;" :: "r"(dst), "l"(src));
}
#define CP_COMMIT() asm volatile("cp.async.commit_group;" ::: "memory")
#define CP_WAIT1()  asm volatile("cp.async.wait_group 1;" ::: "memory")

__device__ __forceinline__ void ldsm4(uint32_t* r, uint32_t a) {
    asm volatile("ldmatrix.sync.aligned.m8n8.x4.shared.b16 {%0,%1,%2,%3}, [%4];"
                 : "=r"(r[0]), "=r"(r[1]), "=r"(r[2]), "=r"(r[3]) : "r"(a));
}
__device__ __forceinline__ void ldsm4t(uint32_t* r, uint32_t a) {
    asm volatile("ldmatrix.sync.aligned.m8n8.x4.trans.shared.b16 {%0,%1,%2,%3}, [%4];"
                 : "=r"(r[0]), "=r"(r[1]), "=r"(r[2]), "=r"(r[3]) : "r"(a));
}
__device__ __forceinline__ void hmma(float* d, const uint32_t* a, const uint32_t* b) {
    asm volatile("mma.sync.aligned.m16n8k16.row.col.f32.f16.f16.f32 "
                 "{%0,%1,%2,%3}, {%4,%5,%6,%7}, {%8,%9}, {%0,%1,%2,%3};"
                 : "+f"(d[0]), "+f"(d[1]), "+f"(d[2]), "+f"(d[3])
                 : "r"(a[0]), "r"(a[1]), "r"(a[2]), "r"(a[3]), "r"(b[0]), "r"(b[1]));
}
__device__ __forceinline__ float ex2(float x) {
    float r;
    asm("ex2.approx.ftz.f32 %0, %1;" : "=f"(r) : "f"(x));
    return r;
}
__device__ __forceinline__ uint32_t h2pack(float a, float b) {
    __half2 h = __floats2half2_rn(a, b);
    return *(uint32_t*)&h;
}

// ---------------- fused prepass: rope(Q), rope(K), conv(V) ----------------
#define QBLK ((TT * HQn * 64) / 256)     // 8192
#define KBLK ((TT * HKVn * 64) / 256)    // 2048
#define VBLK ((TT * HKVn * DH) / 1024)   // 1024
__global__ void prep_kernel(const float* __restrict__ q, const float* __restrict__ k,
                            const float* __restrict__ v, const float* __restrict__ cs,
                            const float* __restrict__ sn) {
    int b = blockIdx.x;
    if (b < QBLK) {
        int lin = b * 256 + threadIdx.x;
        int row = lin >> 6, j = lin & 63;
        int tq = row >> 4;
        size_t base = (size_t)row * DH;
        float2 xv = *(const float2*)(q + base + 2 * j);
        float2 xo = *(const float2*)(q + base + ((2 * j) ^ 64));
        int ci = (2 * j) & 63;
        float c0 = cs[tq * 64 + ci],     s0 = sn[tq * 64 + ci];
        float c1 = cs[tq * 64 + ci + 1], s1 = sn[tq * 64 + ci + 1];
        float sg = (j < 32) ? -1.f : 1.f;
        *(__half2*)(g_qh + base + 2 * j) =
            __floats2half2_rn(xv.x * c0 + sg * xo.x * s0, xv.y * c1 + sg * xo.y * s1);
    } else if (b < QBLK + KBLK) {
        int lin = (b - QBLK) * 256 + threadIdx.x;
        int row = lin >> 6, j = lin & 63;
        int tk = row >> 2;
        size_t base = (size_t)row * DH;
        float2 xv = *(const float2*)(k + base + 2 * j);
        float2 xo = *(const float2*)(k + base + ((2 * j) ^ 64));
        int ci = (2 * j) & 63;
        float c0 = cs[tk * 64 + ci],     s0 = sn[tk * 64 + ci];
        float c1 = cs[tk * 64 + ci + 1], s1 = sn[tk * 64 + ci + 1];
        float sg = (j < 32) ? -1.f : 1.f;
        *(__half2*)(g_kh + base + 2 * j) =
            __floats2half2_rn(xv.x * c0 + sg * xo.x * s0, xv.y * c1 + sg * xo.y * s1);
    } else {
        size_t i = ((size_t)(b - QBLK - KBLK) * 256 + threadIdx.x) * 4;
        float4 f = *(const float4*)(v + i);
        ((__half2*)(g_vh + i))[0] = __floats2half2_rn(f.x, f.y);
        ((__half2*)(g_vh + i))[1] = __floats2half2_rn(f.z, f.w);
    }
}

// ---------------- K/V tile loader (cp.async) ----------------
__device__ __forceinline__ void load_tile(uint32_t sb, int t0, int stage, int hk, int tid) {
    const uint32_t Kb = sb + OFF_K(stage), Vb = sb + OFF_V(stage);
#pragma unroll
    for (int j = 0; j < 4; ++j) {
        int idx = tid + j * 256;
        int row = idx >> 4, c = idx & 15;
        size_t g = ((size_t)(t0 + row) * HKVn + hk) * DH + c * 8;
        uint32_t so = row * 256 + swz(c, row) * 16;
        cpa(Kb + so, g_kh + g);
        cpa(Vb + so, g_vh + g);
    }
}

// ---------------- main attention kernel (split-K, fused reduce) ----------------
__global__ __launch_bounds__(NTH, 1)
void attn_kernel(const int* __restrict__ qranges,
                 const int* __restrict__ kranges,
                 int nR, float* __restrict__ out) {
    extern __shared__ char smem[];
    const uint32_t sb = smem_u32(smem);
    const int tid  = threadIdx.x;
    const int wid  = tid >> 5;
    const int lane = tid & 31;
    const int g    = lane >> 2;
    const int tq4  = lane & 3;

    const int head  = blockIdx.x & 15;
    const int chunk = (blockIdx.x >> 4) & (MAXCH - 1);
    const int qt    = 15 - (blockIdx.x >> 5);   // heavy-first
    const int q0    = qt * BM;
    const int hk    = head >> 2;

    int kEnd = 0;
    for (int r = 0; r < nR; ++r) {
        int qs = qranges[2 * r], qe = qranges[2 * r + 1];
        if (q0 >= qs && q0 < qe) { int ke = kranges[2 * r + 1]; if (ke > kEnd) kEnd = ke; }
    }
    const int nt  = kEnd / BN;
    const int nch = (nt + CHUNK_TILES - 1) / CHUNK_TILES;
    if (chunk >= nch) return;
    const int csz = (nt + nch - 1) / nch;       // balanced chunk size
    const int tS = chunk * csz;
    const int tE = min(nt, tS + csz);

    const int mwBase = wid * 16;               // 16 q rows per warp, all 64 keys

    // ---- prologue: group0 = Q + tile0, group1 = tile1 ----
#pragma unroll
    for (int j = 0; j < 8; ++j) {
        int idx = tid + j * 256;
        int row = idx >> 4, c = idx & 15;
        size_t gof = ((size_t)(q0 + row) * HQn + head) * DH + c * 8;
        cpa(sb + OFF_Q + row * 256 + swz(c, row) * 16, g_qh + gof);
    }
    load_tile(sb, tS * BN, 0, hk, tid);
    CP_COMMIT();                               // group: Q + T0
    if (tS + 1 < tE) load_tile(sb, (tS + 1) * BN, 1, hk, tid);
    CP_COMMIT();                               // group: T1 (possibly empty)

    CP_WAIT1();                                // Q + T0 resident
    __syncthreads();

    // ---- cache Q fragments in registers: 16 rows x 128 d = 32 regs ----
    uint32_t Qr[8][4];
    {
        const uint32_t Qb = sb + OFF_Q;
        int rowA = mwBase + (lane & 15);
#pragma unroll
        for (int ks = 0; ks < 8; ++ks) {
            int ch = 2 * ks + (lane >> 4);
            ldsm4(Qr[ks], Qb + rowA * 256 + swz(ch, rowA) * 16);
        }
    }

    float O[16][4];          // 16 rows x 128 d
    float Lacc[4];           // row-sum accumulator via ones-HMMA (col 0)
    const uint32_t ones2[2] = { 0x3C003C00u, 0x3C003C00u };
#pragma unroll
    for (int nf = 0; nf < 16; ++nf)
#pragma unroll
        for (int e = 0; e < 4; ++e) O[nf][e] = 0.f;
#pragma unroll
    for (int e = 0; e < 4; ++e) Lacc[e] = 0.f;

    const float kC = 0.127532019f;   // log2(e)/sqrt(128)

    for (int t = tS; t < tE; ++t) {
        const int s = (t - tS) % 3;

        if (t > tS) {
            CP_WAIT1();                        // tile t resident (t+1 may be in flight)
            __syncthreads();                   // all warps done with tile t-1's stage
        }
        if (t + 2 < tE) { load_tile(sb, (t + 2) * BN, (t + 2 - tS) % 3, hk, tid); }
        CP_COMMIT();                           // keep group count in lockstep

        // ---------- QK: S(m16 x n64) = Q . K^T ----------
        float S[8][4];
#pragma unroll
        for (int nf = 0; nf < 8; ++nf)
#pragma unroll
            for (int e = 0; e < 4; ++e) S[nf][e] = 0.f;

        const uint32_t Kb = sb + OFF_K(s);
#pragma unroll
        for (int ks = 0; ks < 8; ++ks) {
            uint32_t kb[16];
#pragma unroll
            for (int kk = 0; kk < 4; ++kk) {
                int rowK = kk * 16 + ((lane >> 4) << 3) + (lane & 7);
                int ch = 2 * ks + ((lane >> 3) & 1);
                ldsm4(kb + 4 * kk, Kb + rowK * 256 + swz(ch, rowK) * 16);
            }
#pragma unroll
            for (int nf = 0; nf < 8; ++nf)
                hmma(S[nf], Qr[ks], kb + 2 * nf);
        }

        // ---------- softmax: S C-frags -> P A-frags in registers (FA-2 trick) ----------
        uint32_t Pa[4][4];
#pragma unroll
        for (int j = 0; j < 4; ++j) {
            float e00 = ex2(S[2 * j][0] * kC),     e01 = ex2(S[2 * j][1] * kC);
            float e02 = ex2(S[2 * j][2] * kC),     e03 = ex2(S[2 * j][3] * kC);
            float e10 = ex2(S[2 * j + 1][0] * kC), e11 = ex2(S[2 * j + 1][1] * kC);
            float e12 = ex2(S[2 * j + 1][2] * kC), e13 = ex2(S[2 * j + 1][3] * kC);
            Pa[j][0] = h2pack(e00, e01);
            Pa[j][1] = h2pack(e02, e03);
            Pa[j][2] = h2pack(e10, e11);
            Pa[j][3] = h2pack(e12, e13);
        }

        // ---------- PV: O(m16 x d128) += P . V ; l via ones column ----------
        const uint32_t Vb = sb + OFF_V(s);
#pragma unroll
        for (int ks = 0; ks < 4; ++ks) {
            uint32_t vb[32];
            hmma(Lacc, Pa[ks], ones2);
#pragma unroll
            for (int j = 0; j < 8; ++j) {
                int rowV = ks * 16 + (lane & 15);
                int cd = j * 2 + (lane >> 4);
                ldsm4t(vb + 4 * j, Vb + rowV * 256 + swz(cd, rowV) * 16);
            }
#pragma unroll
            for (int nf = 0; nf < 16; ++nf)
                hmma(O[nf], Pa[ks], vb + 2 * nf);
        }
    }

    // l per row: col 0 of Lacc lives in tq4==0 lanes (c0 -> row rg, c2 -> row rg+8)
    const int rg = mwBase + g;
    const int rh = rg + 8;
    const float lg = __shfl_sync(0xffffffffu, Lacc[0], lane & ~3);
    const float lh = __shfl_sync(0xffffffffu, Lacc[2], lane & ~3);

    if (nch == 1) {
        // ---- direct epilogue: normalize + store ----
        float ig = 1.0f / lg;
        float ih = 1.0f / lh;
        float* og = out + ((size_t)(q0 + rg) * HQn + head) * DH;
        float* oh = out + ((size_t)(q0 + rh) * HQn + head) * DH;
#pragma unroll
        for (int nf = 0; nf < 16; ++nf) {
            int d = nf * 8 + 2 * tq4;
            *(float2*)(og + d) = make_float2(O[nf][0] * ig, O[nf][1] * ig);
            *(float2*)(oh + d) = make_float2(O[nf][2] * ih, O[nf][3] * ih);
        }
        return;
    }

    // ---- split epilogue: unnormalized partial O + l to scratch ----
    const int hq16 = head * 16 + qt;
    const size_t base = (size_t)hq16 * MAXCH;
    {
        float* po = g_po + (base + chunk) * (BM * DH);
        float* pl = g_pl + (base + chunk) * BM;
        if (tq4 == 0) { pl[rg] = lg; pl[rh] = lh; }
        float* og = po + rg * DH;
        float* oh = po + rh * DH;
#pragma unroll
        for (int nf = 0; nf < 16; ++nf) {
            int d = nf * 8 + 2 * tq4;
            *(float2*)(og + d) = make_float2(O[nf][0], O[nf][1]);
            *(float2*)(oh + d) = make_float2(O[nf][2], O[nf][3]);
        }
    }

    // ---- election: last-arriving chunk reduces ----
    __threadfence();
    __syncthreads();
    int* flag = (int*)(smem + OFF_FLAG);
    if (tid == 0) *flag = atomicAdd(&g_cnt[hq16], 1);
    __syncthreads();
    if (*flag != nch - 1) return;

    // this CTA is the reducer
    if (tid == 0) g_cnt[hq16] = 0;             // reset for next graph replay
    __threadfence();
    float* linv = (float*)(smem + OFF_LB);
    if (tid < BM) {
        float l = 0.f;
        for (int c = 0; c < nch; ++c) l += g_pl[(base + c) * BM + tid];
        linv[tid] = 1.0f / l;
    }
    __syncthreads();

    const float4* po4 = (const float4*)(g_po + base * (BM * DH));
#pragma unroll
    for (int i = 0; i < 16; ++i) {
        int idx = tid + i * 256;               // 4096 float4 = 128x128
        int row = idx >> 5;
        float4 acc = po4[idx];
        for (int c = 1; c < nch; ++c) {
            float4 w = po4[(size_t)c * (BM * DH / 4) + idx];
            acc.x += w.x; acc.y += w.y; acc.z += w.z; acc.w += w.w;
        }
        float sc = linv[row];
        acc.x *= sc; acc.y *= sc; acc.z *= sc; acc.w *= sc;
        int d = (idx & 31) * 4;
        *(float4*)(out + ((size_t)(q0 + row) * HQn + head) * DH + d) = acc;
    }
}

extern "C" void kernel_launch(void* const* d_in, const int* in_sizes, int n_in,
                              void* d_out, int out_size) {
    const float* q  = (const float*)d_in[0];
    const float* k  = (const float*)d_in[1];
    const float* v  = (const float*)d_in[2];
    const float* cs = (const float*)d_in[3];
    const float* sn = (const float*)d_in[4];
    const int*   qr = (const int*)d_in[5];
    const int*   kr = (const int*)d_in[6];
    const int nR = in_sizes[5] / 2;
    float* out = (float*)d_out;

    cudaFuncSetAttribute(attn_kernel,
                         cudaFuncAttributeMaxDynamicSharedMemorySize, SMEM_TOTAL);

    prep_kernel<<<QBLK + KBLK + VBLK, 256>>>(q, k, v, cs, sn);
    attn_kernel<<<(TT / BM) * HQn * MAXCH, NTH, SMEM_TOTAL>>>(qr, kr, nR, out);
}

// round 14
// speedup vs baseline: 1.0995x; 1.0267x over previous
#include <cuda_runtime.h>
#include <cuda_fp16.h>
#include <cstdint>

#define TT   2048
#define HQn  16
#define HKVn 4
#define DH   128
#define BM   128
#define BN   64
#define NTH  256
#define CHUNK_TILES 16          // max key-tiles per split-K chunk
#define MAXCH 2                 // max chunks per (head, q-tile)

// ---------------- smem layout (bytes) ----------------
#define OFF_Q    0                          // 32KB (only used in prologue)
#define OFF_K(s) (32768 + (s) * 32768)      // 3 stages x (16K K + 16K V)
#define OFF_V(s) (OFF_K(s) + 16384)
#define OFF_LB   131072                     // reducer l staging (512B)
#define OFF_FLAG 131584                     // int flag for reducer election
#define SMEM_TOTAL 132096

// ---------------- global scratch ----------------
__device__ __align__(16) __half g_qh[(size_t)TT * HQn * DH];
__device__ __align__(16) __half g_kh[(size_t)TT * HKVn * DH];
__device__ __align__(16) __half g_vh[(size_t)TT * HKVn * DH];
// split-K partials: slot = ((head*16 + qt)*MAXCH + chunk)
__device__ __align__(16) float g_po[(size_t)HQn * 16 * MAXCH * BM * DH];
__device__ float g_pl[(size_t)HQn * 16 * MAXCH * BM];
__device__ int   g_cnt[HQn * 16];   // zero-init; reducer resets after use

// ---------------- helpers ----------------
__device__ __forceinline__ uint32_t smem_u32(const void* p) {
    uint32_t a;
    asm("{ .reg .u64 t; cvta.to.shared.u64 t, %1; cvt.u32.u64 %0, t; }" : "=r"(a) : "l"(p));
    return a;
}
__device__ __forceinline__ int swz(int c, int row) {      // 16B-chunk swizzle
    return (c & 8) | ((c ^ row) & 7);
}
__device__ __forceinline__ void cpa(uint32_t dst, const void* src) {
    asm volatile("cp.async.cg.shared.global [%0], [%1], 16;" :: "r"(dst), "l"(src));
}
#define CP_COMMIT() asm volatile("cp.async.commit_group;" ::: "memory")
#define CP_WAIT1()  asm volatile("cp.async.wait_group 1;" ::: "memory")

__device__ __forceinline__ void ldsm4(uint32_t* r, uint32_t a) {
    asm volatile("ldmatrix.sync.aligned.m8n8.x4.shared.b16 {%0,%1,%2,%3}, [%4];"
                 : "=r"(r[0]), "=r"(r[1]), "=r"(r[2]), "=r"(r[3]) : "r"(a));
}
__device__ __forceinline__ void ldsm4t(uint32_t* r, uint32_t a) {
    asm volatile("ldmatrix.sync.aligned.m8n8.x4.trans.shared.b16 {%0,%1,%2,%3}, [%4];"
                 : "=r"(r[0]), "=r"(r[1]), "=r"(r[2]), "=r"(r[3]) : "r"(a));
}
__device__ __forceinline__ void hmma(float* d, const uint32_t* a, const uint32_t* b) {
    asm volatile("mma.sync.aligned.m16n8k16.row.col.f32.f16.f16.f32 "
                 "{%0,%1,%2,%3}, {%4,%5,%6,%7}, {%8,%9}, {%0,%1,%2,%3};"
                 : "+f"(d[0]), "+f"(d[1]), "+f"(d[2]), "+f"(d[3])
                 : "r"(a[0]), "r"(a[1]), "r"(a[2]), "r"(a[3]), "r"(b[0]), "r"(b[1]));
}
__device__ __forceinline__ float ex2(float x) {
    float r;
    asm("ex2.approx.ftz.f32 %0, %1;" : "=f"(r) : "f"(x));
    return r;
}
__device__ __forceinline__ uint32_t h2pack(float a, float b) {
    __half2 h = __floats2half2_rn(a, b);
    return *(uint32_t*)&h;
}

// ---------------- fused prepass: rope(Q), rope(K), conv(V) ----------------
#define QBLK ((TT * HQn * 64) / 256)     // 8192
#define KBLK ((TT * HKVn * 64) / 256)    // 2048
#define VBLK ((TT * HKVn * DH) / 1024)   // 1024
__global__ void prep_kernel(const float* __restrict__ q, const float* __restrict__ k,
                            const float* __restrict__ v, const float* __restrict__ cs,
                            const float* __restrict__ sn) {
    int b = blockIdx.x;
    if (b < QBLK) {
        int lin = b * 256 + threadIdx.x;
        int row = lin >> 6, j = lin & 63;
        int tq = row >> 4;
        size_t base = (size_t)row * DH;
        float2 xv = *(const float2*)(q + base + 2 * j);
        float2 xo = *(const float2*)(q + base + ((2 * j) ^ 64));
        int ci = (2 * j) & 63;
        float c0 = cs[tq * 64 + ci],     s0 = sn[tq * 64 + ci];
        float c1 = cs[tq * 64 + ci + 1], s1 = sn[tq * 64 + ci + 1];
        float sg = (j < 32) ? -1.f : 1.f;
        *(__half2*)(g_qh + base + 2 * j) =
            __floats2half2_rn(xv.x * c0 + sg * xo.x * s0, xv.y * c1 + sg * xo.y * s1);
    } else if (b < QBLK + KBLK) {
        int lin = (b - QBLK) * 256 + threadIdx.x;
        int row = lin >> 6, j = lin & 63;
        int tk = row >> 2;
        size_t base = (size_t)row * DH;
        float2 xv = *(const float2*)(k + base + 2 * j);
        float2 xo = *(const float2*)(k + base + ((2 * j) ^ 64));
        int ci = (2 * j) & 63;
        float c0 = cs[tk * 64 + ci],     s0 = sn[tk * 64 + ci];
        float c1 = cs[tk * 64 + ci + 1], s1 = sn[tk * 64 + ci + 1];
        float sg = (j < 32) ? -1.f : 1.f;
        *(__half2*)(g_kh + base + 2 * j) =
            __floats2half2_rn(xv.x * c0 + sg * xo.x * s0, xv.y * c1 + sg * xo.y * s1);
    } else {
        size_t i = ((size_t)(b - QBLK - KBLK) * 256 + threadIdx.x) * 4;
        float4 f = *(const float4*)(v + i);
        ((__half2*)(g_vh + i))[0] = __floats2half2_rn(f.x, f.y);
        ((__half2*)(g_vh + i))[1] = __floats2half2_rn(f.z, f.w);
    }
}

// ---------------- K/V tile loader (cp.async) ----------------
__device__ __forceinline__ void load_tile(uint32_t sb, int t0, int stage, int hk, int tid) {
    const uint32_t Kb = sb + OFF_K(stage), Vb = sb + OFF_V(stage);
#pragma unroll
    for (int j = 0; j < 4; ++j) {
        int idx = tid + j * 256;
        int row = idx >> 4, c = idx & 15;
        size_t g = ((size_t)(t0 + row) * HKVn + hk) * DH + c * 8;
        uint32_t so = row * 256 + swz(c, row) * 16;
        cpa(Kb + so, g_kh + g);
        cpa(Vb + so, g_vh + g);
    }
}

// ---------------- main attention kernel (split-K, fused reduce) ----------------
__global__ __launch_bounds__(NTH, 1)
void attn_kernel(const int* __restrict__ qranges,
                 const int* __restrict__ kranges,
                 int nR, float* __restrict__ out) {
    extern __shared__ char smem[];
    const uint32_t sb = smem_u32(smem);
    const int tid  = threadIdx.x;
    const int wid  = tid >> 5;
    const int lane = tid & 31;
    const int g    = lane >> 2;
    const int tq4  = lane & 3;

    const int head  = blockIdx.x & 15;
    const int chunk = (blockIdx.x >> 4) & (MAXCH - 1);
    const int qt    = 15 - (blockIdx.x >> 5);   // heavy-first
    const int q0    = qt * BM;
    const int hk    = head >> 2;

    int kEnd = 0;
    for (int r = 0; r < nR; ++r) {
        int qs = qranges[2 * r], qe = qranges[2 * r + 1];
        if (q0 >= qs && q0 < qe) { int ke = kranges[2 * r + 1]; if (ke > kEnd) kEnd = ke; }
    }
    const int nt  = kEnd / BN;
    const int nch = (nt + CHUNK_TILES - 1) / CHUNK_TILES;
    if (chunk >= nch) return;
    const int csz = (nt + nch - 1) / nch;       // balanced chunk size
    const int tS = chunk * csz;
    const int tE = min(nt, tS + csz);

    const int mwBase = wid * 16;               // 16 q rows per warp, all 64 keys

    // ---- prologue: group0 = Q + tile0, group1 = tile1 ----
#pragma unroll
    for (int j = 0; j < 8; ++j) {
        int idx = tid + j * 256;
        int row = idx >> 4, c = idx & 15;
        size_t gof = ((size_t)(q0 + row) * HQn + head) * DH + c * 8;
        cpa(sb + OFF_Q + row * 256 + swz(c, row) * 16, g_qh + gof);
    }
    load_tile(sb, tS * BN, 0, hk, tid);
    CP_COMMIT();                               // group: Q + T0
    if (tS + 1 < tE) load_tile(sb, (tS + 1) * BN, 1, hk, tid);
    CP_COMMIT();                               // group: T1 (possibly empty)

    CP_WAIT1();                                // Q + T0 resident
    __syncthreads();

    // ---- cache Q fragments in registers: 16 rows x 128 d = 32 regs ----
    uint32_t Qr[8][4];
    {
        const uint32_t Qb = sb + OFF_Q;
        int rowA = mwBase + (lane & 15);
#pragma unroll
        for (int ks = 0; ks < 8; ++ks) {
            int ch = 2 * ks + (lane >> 4);
            ldsm4(Qr[ks], Qb + rowA * 256 + swz(ch, rowA) * 16);
        }
    }

    float O[16][4];          // 16 rows x 128 d
    float Lacc[4];           // row-sum accumulator via ones-HMMA (col 0)
    const uint32_t ones2[2] = { 0x3C003C00u, 0x3C003C00u };
#pragma unroll
    for (int nf = 0; nf < 16; ++nf)
#pragma unroll
        for (int e = 0; e < 4; ++e) O[nf][e] = 0.f;
#pragma unroll
    for (int e = 0; e < 4; ++e) Lacc[e] = 0.f;

    const float kC = 0.127532019f;   // log2(e)/sqrt(128)

    for (int t = tS; t < tE; ++t) {
        const int s = (t - tS) % 3;

        if (t > tS) {
            CP_WAIT1();                        // tile t resident (t+1 may be in flight)
            __syncthreads();                   // all warps done with tile t-1's stage
        }
        if (t + 2 < tE) { load_tile(sb, (t + 2) * BN, (t + 2 - tS) % 3, hk, tid); }
        CP_COMMIT();                           // keep group count in lockstep

        // ---------- QK: S(m16 x n64) = Q . K^T (double-buffered K frags) ----------
        float S[8][4];
#pragma unroll
        for (int nf = 0; nf < 8; ++nf)
#pragma unroll
            for (int e = 0; e < 4; ++e) S[nf][e] = 0.f;

        const uint32_t Kb = sb + OFF_K(s);
        uint32_t kb[2][16];
        {
            // preload ks = 0
            int ch0 = (lane >> 3) & 1;
#pragma unroll
            for (int kk = 0; kk < 4; ++kk) {
                int rowK = kk * 16 + ((lane >> 4) << 3) + (lane & 7);
                ldsm4(kb[0] + 4 * kk, Kb + rowK * 256 + swz(ch0, rowK) * 16);
            }
        }
#pragma unroll
        for (int ks = 0; ks < 8; ++ks) {
            const int cur = ks & 1;
            if (ks < 7) {
                int ch = 2 * (ks + 1) + ((lane >> 3) & 1);
#pragma unroll
                for (int kk = 0; kk < 4; ++kk) {
                    int rowK = kk * 16 + ((lane >> 4) << 3) + (lane & 7);
                    ldsm4(kb[cur ^ 1] + 4 * kk, Kb + rowK * 256 + swz(ch, rowK) * 16);
                }
            }
#pragma unroll
            for (int nf = 0; nf < 8; ++nf)
                hmma(S[nf], Qr[ks], kb[cur] + 2 * nf);
        }

        // ---------- softmax: S C-frags -> P A-frags in registers (FA-2 trick) ----------
        uint32_t Pa[4][4];
#pragma unroll
        for (int j = 0; j < 4; ++j) {
            float e00 = ex2(S[2 * j][0] * kC),     e01 = ex2(S[2 * j][1] * kC);
            float e02 = ex2(S[2 * j][2] * kC),     e03 = ex2(S[2 * j][3] * kC);
            float e10 = ex2(S[2 * j + 1][0] * kC), e11 = ex2(S[2 * j + 1][1] * kC);
            float e12 = ex2(S[2 * j + 1][2] * kC), e13 = ex2(S[2 * j + 1][3] * kC);
            Pa[j][0] = h2pack(e00, e01);
            Pa[j][1] = h2pack(e02, e03);
            Pa[j][2] = h2pack(e10, e11);
            Pa[j][3] = h2pack(e12, e13);
        }

        // ---------- PV: O(m16 x d128) += P . V ; l via ones column ----------
        // 8 chunks (c = ks*2 + half), vb double-buffered
        const uint32_t Vb = sb + OFF_V(s);
        uint32_t vb[2][16];
        {
            // preload chunk 0 (ks=0, half=0)
            int rowV = (lane & 15);
#pragma unroll
            for (int j = 0; j < 4; ++j) {
                int cd = j * 2 + (lane >> 4);
                ldsm4t(vb[0] + 4 * j, Vb + rowV * 256 + swz(cd, rowV) * 16);
            }
        }
#pragma unroll
        for (int c = 0; c < 8; ++c) {
            const int cur = c & 1;
            if (c < 7) {
                int nks = (c + 1) >> 1, nhalf = (c + 1) & 1;
                int rowV = nks * 16 + (lane & 15);
#pragma unroll
                for (int j = 0; j < 4; ++j) {
                    int cd = nhalf * 8 + j * 2 + (lane >> 4);
                    ldsm4t(vb[cur ^ 1] + 4 * j, Vb + rowV * 256 + swz(cd, rowV) * 16);
                }
            }
            const int ks = c >> 1, half = c & 1;
            if (half == 0) hmma(Lacc, Pa[ks], ones2);
#pragma unroll
            for (int nf = 0; nf < 8; ++nf)
                hmma(O[half * 8 + nf], Pa[ks], vb[cur] + 2 * nf);
        }
    }

    // l per row: col 0 of Lacc lives in tq4==0 lanes (c0 -> row rg, c2 -> row rg+8)
    const int rg = mwBase + g;
    const int rh = rg + 8;
    const float lg = __shfl_sync(0xffffffffu, Lacc[0], lane & ~3);
    const float lh = __shfl_sync(0xffffffffu, Lacc[2], lane & ~3);

    if (nch == 1) {
        // ---- direct epilogue: normalize + store ----
        float ig = 1.0f / lg;
        float ih = 1.0f / lh;
        float* og = out + ((size_t)(q0 + rg) * HQn + head) * DH;
        float* oh = out + ((size_t)(q0 + rh) * HQn + head) * DH;
#pragma unroll
        for (int nf = 0; nf < 16; ++nf) {
            int d = nf * 8 + 2 * tq4;
            *(float2*)(og + d) = make_float2(O[nf][0] * ig, O[nf][1] * ig);
            *(float2*)(oh + d) = make_float2(O[nf][2] * ih, O[nf][3] * ih);
        }
        return;
    }

    // ---- split epilogue: unnormalized partial O + l to scratch ----
    const int hq16 = head * 16 + qt;
    const size_t base = (size_t)hq16 * MAXCH;
    {
        float* po = g_po + (base + chunk) * (BM * DH);
        float* pl = g_pl + (base + chunk) * BM;
        if (tq4 == 0) { pl[rg] = lg; pl[rh] = lh; }
        float* og = po + rg * DH;
        float* oh = po + rh * DH;
#pragma unroll
        for (int nf = 0; nf < 16; ++nf) {
            int d = nf * 8 + 2 * tq4;
            *(float2*)(og + d) = make_float2(O[nf][0], O[nf][1]);
            *(float2*)(oh + d) = make_float2(O[nf][2], O[nf][3]);
        }
    }

    // ---- election: last-arriving chunk reduces ----
    __threadfence();
    __syncthreads();
    int* flag = (int*)(smem + OFF_FLAG);
    if (tid == 0) *flag = atomicAdd(&g_cnt[hq16], 1);
    __syncthreads();
    if (*flag != nch - 1) return;

    // this CTA is the reducer
    if (tid == 0) g_cnt[hq16] = 0;             // reset for next graph replay
    __threadfence();
    float* linv = (float*)(smem + OFF_LB);
    if (tid < BM) {
        float l = 0.f;
        for (int c = 0; c < nch; ++c) l += g_pl[(base + c) * BM + tid];
        linv[tid] = 1.0f / l;
    }
    __syncthreads();

    const float4* po4 = (const float4*)(g_po + base * (BM * DH));
#pragma unroll
    for (int i = 0; i < 16; ++i) {
        int idx = tid + i * 256;               // 4096 float4 = 128x128
        int row = idx >> 5;
        float4 acc = po4[idx];
        for (int c = 1; c < nch; ++c) {
            float4 w = po4[(size_t)c * (BM * DH / 4) + idx];
            acc.x += w.x; acc.y += w.y; acc.z += w.z; acc.w += w.w;
        }
        float sc = linv[row];
        acc.x *= sc; acc.y *= sc; acc.z *= sc; acc.w *= sc;
        int d = (idx & 31) * 4;
        *(float4*)(out + ((size_t)(q0 + row) * HQn + head) * DH + d) = acc;
    }
}

extern "C" void kernel_launch(void* const* d_in, const int* in_sizes, int n_in,
                              void* d_out, int out_size) {
    const float* q  = (const float*)d_in[0];
    const float* k  = (const float*)d_in[1];
    const float* v  = (const float*)d_in[2];
    const float* cs = (const float*)d_in[3];
    const float* sn = (const float*)d_in[4];
    const int*   qr = (const int*)d_in[5];
    const int*   kr = (const int*)d_in[6];
    const int nR = in_sizes[5] / 2;
    float* out = (float*)d_out;

    cudaFuncSetAttribute(attn_kernel,
                         cudaFuncAttributeMaxDynamicSharedMemorySize, SMEM_TOTAL);

    prep_kernel<<<QBLK + KBLK + VBLK, 256>>>(q, k, v, cs, sn);
    attn_kernel<<<(TT / BM) * HQn * MAXCH, NTH, SMEM_TOTAL>>>(qr, kr, nR, out);
}

// round 15
// speedup vs baseline: 1.1086x; 1.0083x over previous
#include <cuda_runtime.h>
#include <cuda_fp16.h>
#include <cstdint>

#define TT   2048
#define HQn  16
#define HKVn 4
#define DH   128
#define BM   128
#define BN   64
#define NTH  256
#define CHUNK_TILES 16          // max key-tiles per split-K chunk
#define MAXCH 2                 // max chunks per (head, q-tile)

// ---------------- smem layout (bytes) ----------------
#define OFF_Q    0                          // 32KB (only used in prologue)
#define OFF_K(s) (32768 + (s) * 32768)      // 4 stages x (16K K + 16K V)
#define OFF_V(s) (OFF_K(s) + 16384)
#define OFF_LB   163840                     // reducer l staging (512B)
#define OFF_FLAG 164352                     // int flag for reducer election
#define SMEM_TOTAL 164864

// ---------------- global scratch ----------------
__device__ __align__(16) __half g_qh[(size_t)TT * HQn * DH];
__device__ __align__(16) __half g_kh[(size_t)TT * HKVn * DH];
__device__ __align__(16) __half g_vh[(size_t)TT * HKVn * DH];
// split-K partials: slot = ((head*16 + qt)*MAXCH + chunk)
__device__ __align__(16) float g_po[(size_t)HQn * 16 * MAXCH * BM * DH];
__device__ float g_pl[(size_t)HQn * 16 * MAXCH * BM];
__device__ int   g_cnt[HQn * 16];   // zero-init; reducer resets after use

// ---------------- helpers ----------------
__device__ __forceinline__ uint32_t smem_u32(const void* p) {
    uint32_t a;
    asm("{ .reg .u64 t; cvta.to.shared.u64 t, %1; cvt.u32.u64 %0, t; }" : "=r"(a) : "l"(p));
    return a;
}
__device__ __forceinline__ int swz(int c, int row) {      // 16B-chunk swizzle
    return (c & 8) | ((c ^ row) & 7);
}
__device__ __forceinline__ void cpa(uint32_t dst, const void* src) {
    asm volatile("cp.async.cg.shared.global [%0], [%1], 16;" :: "r"(dst), "l"(src));
}
#define CP_COMMIT() asm volatile("cp.async.commit_group;" ::: "memory")
#define CP_WAIT1()  asm volatile("cp.async.wait_group 1;" ::: "memory")

__device__ __forceinline__ void ldsm4(uint32_t* r, uint32_t a) {
    asm volatile("ldmatrix.sync.aligned.m8n8.x4.shared.b16 {%0,%1,%2,%3}, [%4];"
                 : "=r"(r[0]), "=r"(r[1]), "=r"(r[2]), "=r"(r[3]) : "r"(a));
}
__device__ __forceinline__ void ldsm4t(uint32_t* r, uint32_t a) {
    asm volatile("ldmatrix.sync.aligned.m8n8.x4.trans.shared.b16 {%0,%1,%2,%3}, [%4];"
                 : "=r"(r[0]), "=r"(r[1]), "=r"(r[2]), "=r"(r[3]) : "r"(a));
}
__device__ __forceinline__ void hmma(float* d, const uint32_t* a, const uint32_t* b) {
    asm volatile("mma.sync.aligned.m16n8k16.row.col.f32.f16.f16.f32 "
                 "{%0,%1,%2,%3}, {%4,%5,%6,%7}, {%8,%9}, {%0,%1,%2,%3};"
                 : "+f"(d[0]), "+f"(d[1]), "+f"(d[2]), "+f"(d[3])
                 : "r"(a[0]), "r"(a[1]), "r"(a[2]), "r"(a[3]), "r"(b[0]), "r"(b[1]));
}
__device__ __forceinline__ float ex2(float x) {
    float r;
    asm("ex2.approx.ftz.f32 %0, %1;" : "=f"(r) : "f"(x));
    return r;
}
__device__ __forceinline__ uint32_t h2pack(float a, float b) {
    __half2 h = __floats2half2_rn(a, b);
    return *(uint32_t*)&h;
}

// ---------------- fused prepass: rope(Q), rope(K), conv(V) ----------------
#define QBLK ((TT * HQn * 64) / 256)     // 8192
#define KBLK ((TT * HKVn * 64) / 256)    // 2048
#define VBLK ((TT * HKVn * DH) / 1024)   // 1024
__global__ void prep_kernel(const float* __restrict__ q, const float* __restrict__ k,
                            const float* __restrict__ v, const float* __restrict__ cs,
                            const float* __restrict__ sn) {
    int b = blockIdx.x;
    if (b < QBLK) {
        int lin = b * 256 + threadIdx.x;
        int row = lin >> 6, j = lin & 63;
        int tq = row >> 4;
        size_t base = (size_t)row * DH;
        float2 xv = *(const float2*)(q + base + 2 * j);
        float2 xo = *(const float2*)(q + base + ((2 * j) ^ 64));
        int ci = (2 * j) & 63;
        float c0 = cs[tq * 64 + ci],     s0 = sn[tq * 64 + ci];
        float c1 = cs[tq * 64 + ci + 1], s1 = sn[tq * 64 + ci + 1];
        float sg = (j < 32) ? -1.f : 1.f;
        *(__half2*)(g_qh + base + 2 * j) =
            __floats2half2_rn(xv.x * c0 + sg * xo.x * s0, xv.y * c1 + sg * xo.y * s1);
    } else if (b < QBLK + KBLK) {
        int lin = (b - QBLK) * 256 + threadIdx.x;
        int row = lin >> 6, j = lin & 63;
        int tk = row >> 2;
        size_t base = (size_t)row * DH;
        float2 xv = *(const float2*)(k + base + 2 * j);
        float2 xo = *(const float2*)(k + base + ((2 * j) ^ 64));
        int ci = (2 * j) & 63;
        float c0 = cs[tk * 64 + ci],     s0 = sn[tk * 64 + ci];
        float c1 = cs[tk * 64 + ci + 1], s1 = sn[tk * 64 + ci + 1];
        float sg = (j < 32) ? -1.f : 1.f;
        *(__half2*)(g_kh + base + 2 * j) =
            __floats2half2_rn(xv.x * c0 + sg * xo.x * s0, xv.y * c1 + sg * xo.y * s1);
    } else {
        size_t i = ((size_t)(b - QBLK - KBLK) * 256 + threadIdx.x) * 4;
        float4 f = *(const float4*)(v + i);
        ((__half2*)(g_vh + i))[0] = __floats2half2_rn(f.x, f.y);
        ((__half2*)(g_vh + i))[1] = __floats2half2_rn(f.z, f.w);
    }
}

// ---------------- K/V tile loader (cp.async) ----------------
__device__ __forceinline__ void load_tile(uint32_t sb, int t0, int stage, int hk, int tid) {
    const uint32_t Kb = sb + OFF_K(stage), Vb = sb + OFF_V(stage);
#pragma unroll
    for (int j = 0; j < 4; ++j) {
        int idx = tid + j * 256;
        int row = idx >> 4, c = idx & 15;
        size_t g = ((size_t)(t0 + row) * HKVn + hk) * DH + c * 8;
        uint32_t so = row * 256 + swz(c, row) * 16;
        cpa(Kb + so, g_kh + g);
        cpa(Vb + so, g_vh + g);
    }
}

// ---------------- main attention kernel (split-K, fused reduce) ----------------
__global__ __launch_bounds__(NTH, 1)
void attn_kernel(const int* __restrict__ qranges,
                 const int* __restrict__ kranges,
                 int nR, float* __restrict__ out) {
    extern __shared__ char smem[];
    const uint32_t sb = smem_u32(smem);
    const int tid  = threadIdx.x;
    const int wid  = tid >> 5;
    const int lane = tid & 31;
    const int g    = lane >> 2;
    const int tq4  = lane & 3;

    const int head  = blockIdx.x & 15;
    const int chunk = (blockIdx.x >> 4) & (MAXCH - 1);
    const int qt    = 15 - (blockIdx.x >> 5);   // heavy-first
    const int q0    = qt * BM;
    const int hk    = head >> 2;

    int kEnd = 0;
    for (int r = 0; r < nR; ++r) {
        int qs = qranges[2 * r], qe = qranges[2 * r + 1];
        if (q0 >= qs && q0 < qe) { int ke = kranges[2 * r + 1]; if (ke > kEnd) kEnd = ke; }
    }
    const int nt  = kEnd / BN;
    const int nch = (nt + CHUNK_TILES - 1) / CHUNK_TILES;
    if (chunk >= nch) return;
    const int csz = (nt + nch - 1) / nch;       // balanced chunk size
    const int tS = chunk * csz;
    const int tE = min(nt, tS + csz);

    const int mwBase = wid * 16;               // 16 q rows per warp, all 64 keys

    // ---- prologue: group0 = Q + tiles {tS, tS+1}; group1 = tiles {tS+2, tS+3} ----
#pragma unroll
    for (int j = 0; j < 8; ++j) {
        int idx = tid + j * 256;
        int row = idx >> 4, c = idx & 15;
        size_t gof = ((size_t)(q0 + row) * HQn + head) * DH + c * 8;
        cpa(sb + OFF_Q + row * 256 + swz(c, row) * 16, g_qh + gof);
    }
    load_tile(sb, tS * BN, 0, hk, tid);
    if (tS + 1 < tE) load_tile(sb, (tS + 1) * BN, 1, hk, tid);
    CP_COMMIT();                               // body-0 group
    if (tS + 2 < tE) load_tile(sb, (tS + 2) * BN, 2, hk, tid);
    if (tS + 3 < tE) load_tile(sb, (tS + 3) * BN, 3, hk, tid);
    CP_COMMIT();                               // body-1 group (possibly empty)

    CP_WAIT1();                                // Q + body-0 tiles resident
    __syncthreads();

    // ---- cache Q fragments in registers: 16 rows x 128 d = 32 regs ----
    uint32_t Qr[8][4];
    {
        const uint32_t Qb = sb + OFF_Q;
        int rowA = mwBase + (lane & 15);
#pragma unroll
        for (int ks = 0; ks < 8; ++ks) {
            int ch = 2 * ks + (lane >> 4);
            ldsm4(Qr[ks], Qb + rowA * 256 + swz(ch, rowA) * 16);
        }
    }

    float O[16][4];          // 16 rows x 128 d
    float Lacc[4];           // row-sum accumulator via ones-HMMA (col 0)
    const uint32_t ones2[2] = { 0x3C003C00u, 0x3C003C00u };
#pragma unroll
    for (int nf = 0; nf < 16; ++nf)
#pragma unroll
        for (int e = 0; e < 4; ++e) O[nf][e] = 0.f;
#pragma unroll
    for (int e = 0; e < 4; ++e) Lacc[e] = 0.f;

    const float kC = 0.127532019f;   // log2(e)/sqrt(128)

    // ---- 2-tile bodies; one barrier + one wait_group per body ----
    for (int tb = tS; tb < tE; tb += 2) {
        if (tb > tS) {
            __syncthreads();                   // all warps done with body i-1 stages
            int tn = tb + 2;                   // body i+1 tiles
            if (tn < tE)     load_tile(sb, tn * BN,       (tn - tS) & 3,     hk, tid);
            if (tn + 1 < tE) load_tile(sb, (tn + 1) * BN, (tn + 1 - tS) & 3, hk, tid);
            CP_COMMIT();
            CP_WAIT1();                        // body i tiles resident
        }

#pragma unroll
        for (int u = 0; u < 2; ++u) {
            const int t = tb + u;
            if (u == 1 && t >= tE) break;
            const int s = (t - tS) & 3;

            // ---------- QK: S(m16 x n64) = Q . K^T (double-buffered K frags) ----------
            float S[8][4];
#pragma unroll
            for (int nf = 0; nf < 8; ++nf)
#pragma unroll
                for (int e = 0; e < 4; ++e) S[nf][e] = 0.f;

            const uint32_t Kb = sb + OFF_K(s);
            uint32_t kb[2][16];
            {
                int ch0 = (lane >> 3) & 1;
#pragma unroll
                for (int kk = 0; kk < 4; ++kk) {
                    int rowK = kk * 16 + ((lane >> 4) << 3) + (lane & 7);
                    ldsm4(kb[0] + 4 * kk, Kb + rowK * 256 + swz(ch0, rowK) * 16);
                }
            }
#pragma unroll
            for (int ks = 0; ks < 8; ++ks) {
                const int cur = ks & 1;
                if (ks < 7) {
                    int ch = 2 * (ks + 1) + ((lane >> 3) & 1);
#pragma unroll
                    for (int kk = 0; kk < 4; ++kk) {
                        int rowK = kk * 16 + ((lane >> 4) << 3) + (lane & 7);
                        ldsm4(kb[cur ^ 1] + 4 * kk, Kb + rowK * 256 + swz(ch, rowK) * 16);
                    }
                }
#pragma unroll
                for (int nf = 0; nf < 8; ++nf)
                    hmma(S[nf], Qr[ks], kb[cur] + 2 * nf);
            }

            // ---------- softmax: S C-frags -> P A-frags in registers ----------
            uint32_t Pa[4][4];
#pragma unroll
            for (int j = 0; j < 4; ++j) {
                float e00 = ex2(S[2 * j][0] * kC),     e01 = ex2(S[2 * j][1] * kC);
                float e02 = ex2(S[2 * j][2] * kC),     e03 = ex2(S[2 * j][3] * kC);
                float e10 = ex2(S[2 * j + 1][0] * kC), e11 = ex2(S[2 * j + 1][1] * kC);
                float e12 = ex2(S[2 * j + 1][2] * kC), e13 = ex2(S[2 * j + 1][3] * kC);
                Pa[j][0] = h2pack(e00, e01);
                Pa[j][1] = h2pack(e02, e03);
                Pa[j][2] = h2pack(e10, e11);
                Pa[j][3] = h2pack(e12, e13);
            }

            // ---------- PV: O(m16 x d128) += P . V ; l via ones column ----------
            const uint32_t Vb = sb + OFF_V(s);
            uint32_t vb[2][16];
            {
                int rowV = (lane & 15);
#pragma unroll
                for (int j = 0; j < 4; ++j) {
                    int cd = j * 2 + (lane >> 4);
                    ldsm4t(vb[0] + 4 * j, Vb + rowV * 256 + swz(cd, rowV) * 16);
                }
            }
#pragma unroll
            for (int c = 0; c < 8; ++c) {
                const int cur = c & 1;
                if (c < 7) {
                    int nks = (c + 1) >> 1, nhalf = (c + 1) & 1;
                    int rowV = nks * 16 + (lane & 15);
#pragma unroll
                    for (int j = 0; j < 4; ++j) {
                        int cd = nhalf * 8 + j * 2 + (lane >> 4);
                        ldsm4t(vb[cur ^ 1] + 4 * j, Vb + rowV * 256 + swz(cd, rowV) * 16);
                    }
                }
                const int ks = c >> 1, half = c & 1;
                if (half == 0) hmma(Lacc, Pa[ks], ones2);
#pragma unroll
                for (int nf = 0; nf < 8; ++nf)
                    hmma(O[half * 8 + nf], Pa[ks], vb[cur] + 2 * nf);
            }
        }
    }

    // l per row: col 0 of Lacc lives in tq4==0 lanes (c0 -> row rg, c2 -> row rg+8)
    const int rg = mwBase + g;
    const int rh = rg + 8;
    const float lg = __shfl_sync(0xffffffffu, Lacc[0], lane & ~3);
    const float lh = __shfl_sync(0xffffffffu, Lacc[2], lane & ~3);

    if (nch == 1) {
        // ---- direct epilogue: normalize + store ----
        float ig = 1.0f / lg;
        float ih = 1.0f / lh;
        float* og = out + ((size_t)(q0 + rg) * HQn + head) * DH;
        float* oh = out + ((size_t)(q0 + rh) * HQn + head) * DH;
#pragma unroll
        for (int nf = 0; nf < 16; ++nf) {
            int d = nf * 8 + 2 * tq4;
            *(float2*)(og + d) = make_float2(O[nf][0] * ig, O[nf][1] * ig);
            *(float2*)(oh + d) = make_float2(O[nf][2] * ih, O[nf][3] * ih);
        }
        return;
    }

    // ---- split epilogue: unnormalized partial O + l to scratch ----
    const int hq16 = head * 16 + qt;
    const size_t base = (size_t)hq16 * MAXCH;
    {
        float* po = g_po + (base + chunk) * (BM * DH);
        float* pl = g_pl + (base + chunk) * BM;
        if (tq4 == 0) { pl[rg] = lg; pl[rh] = lh; }
        float* og = po + rg * DH;
        float* oh = po + rh * DH;
#pragma unroll
        for (int nf = 0; nf < 16; ++nf) {
            int d = nf * 8 + 2 * tq4;
            *(float2*)(og + d) = make_float2(O[nf][0], O[nf][1]);
            *(float2*)(oh + d) = make_float2(O[nf][2], O[nf][3]);
        }
    }

    // ---- election: last-arriving chunk reduces ----
    __threadfence();
    __syncthreads();
    int* flag = (int*)(smem + OFF_FLAG);
    if (tid == 0) *flag = atomicAdd(&g_cnt[hq16], 1);
    __syncthreads();
    if (*flag != nch - 1) return;

    // this CTA is the reducer
    if (tid == 0) g_cnt[hq16] = 0;             // reset for next graph replay
    __threadfence();
    float* linv = (float*)(smem + OFF_LB);
    if (tid < BM) {
        float l = 0.f;
        for (int c = 0; c < nch; ++c) l += g_pl[(base + c) * BM + tid];
        linv[tid] = 1.0f / l;
    }
    __syncthreads();

    const float4* po4 = (const float4*)(g_po + base * (BM * DH));
#pragma unroll
    for (int i = 0; i < 16; ++i) {
        int idx = tid + i * 256;               // 4096 float4 = 128x128
        int row = idx >> 5;
        float4 acc = po4[idx];
        for (int c = 1; c < nch; ++c) {
            float4 w = po4[(size_t)c * (BM * DH / 4) + idx];
            acc.x += w.x; acc.y += w.y; acc.z += w.z; acc.w += w.w;
        }
        float sc = linv[row];
        acc.x *= sc; acc.y *= sc; acc.z *= sc; acc.w *= sc;
        int d = (idx & 31) * 4;
        *(float4*)(out + ((size_t)(q0 + row) * HQn + head) * DH + d) = acc;
    }
}

extern "C" void kernel_launch(void* const* d_in, const int* in_sizes, int n_in,
                              void* d_out, int out_size) {
    const float* q  = (const float*)d_in[0];
    const float* k  = (const float*)d_in[1];
    const float* v  = (const float*)d_in[2];
    const float* cs = (const float*)d_in[3];
    const float* sn = (const float*)d_in[4];
    const int*   qr = (const int*)d_in[5];
    const int*   kr = (const int*)d_in[6];
    const int nR = in_sizes[5] / 2;
    float* out = (float*)d_out;

    cudaFuncSetAttribute(attn_kernel,
                         cudaFuncAttributeMaxDynamicSharedMemorySize, SMEM_TOTAL);

    prep_kernel<<<QBLK + KBLK + VBLK, 256>>>(q, k, v, cs, sn);
    attn_kernel<<<(TT / BM) * HQn * MAXCH, NTH, SMEM_TOTAL>>>(qr, kr, nR, out);
}